// round 16
// baseline (speedup 1.0000x reference)
#include <cuda_runtime.h>
#include <cuda_fp16.h>
#include <mma.h>
#include <cstdint>
#include <cstddef>

using namespace nvcuda;

// ---------------------------------------------------------------------------
// Problem constants
// ---------------------------------------------------------------------------
#define NPOS   32768          // B*H*W*D = 1*32*32*32
#define NSTATE 16
#define DTRANK 8
#define LSEQ   32

// Scratch (device globals; no allocation allowed).
// Serialized per-branch pipeline keeps these L2-resident between kernels.
__device__ __half g_xh [(size_t)NPOS * 128];   // x fp16 (in-proj A)
__device__ __half g_wh [3 * 512 * 128];        // inW, fp16, (512,128) per branch
__device__ __half g_xzh[(size_t)NPOS * 512];   // in-proj out (xi | z), fp16
__device__ __half g_xch[(size_t)NPOS * 256];   // conv+silu xc, fp16 (side-output of fused x-proj)
__device__ __half g_w2h[3 * 128 * 256];        // xpW padded 40->128 rows, per branch
__device__ float  g_P  [(size_t)NPOS * 40];    // x-proj out dbc, ldc=40
__device__ __half g_yh [(size_t)NPOS * 768];   // gated y (3 branches concat per row)
__device__ __half g_Mh [128 * 768];            // folded (outW_t -> fcW) (128,768) fp16

__device__ __forceinline__ float silu_f(float x) {
    return x / (1.f + __expf(-x));
}

// ---------------------------------------------------------------------------
// cp.async helpers
// ---------------------------------------------------------------------------
__device__ __forceinline__ void cp_async16(uint32_t dst_smem, const void* src) {
    asm volatile("cp.async.cg.shared.global [%0], [%1], 16;"
                 :: "r"(dst_smem), "l"(src));
}
__device__ __forceinline__ void cp_commit() {
    asm volatile("cp.async.commit_group;");
}
__device__ __forceinline__ void cp_wait1() {
    asm volatile("cp.async.wait_group 1;");
}

// ===========================================================================
// Double-buffered WMMA fp16 GEMM (cp.async pipeline):
//   C[M,N] = A[M,K](fp16) @ B[N,K](fp16)^T  (fp32 accumulate)
// BM=BN=128, BK=64, 256 threads (8 warps, 64x32 each).
// OUT_HALF=1: fp16 out.  OUT_HALF=0: fp32 out + optional bias.
// ===========================================================================
#define GEMM_BUF_STRIDE 36864
#define GEMM_SMEM_TOTAL 73728

template<bool OUT_HALF>
__global__ void __launch_bounds__(256)
hgemm_db(const __half* __restrict__ A, int lda,
         const __half* __restrict__ B, int ldb,
         void* __restrict__ Cv, int ldc,
         int K, const float* __restrict__ bias, int ncol) {
    extern __shared__ char dsm[];

    const int tid = threadIdx.x;
    const int wid = tid >> 5;
    const int lane = tid & 31;
    const int warp_m = wid & 1;
    const int warp_n = wid >> 1;
    const int bm = blockIdx.y * 128;
    const int bn = blockIdx.x * 128;

    const int lr = tid >> 3;
    const int lc8 = tid & 7;

    wmma::fragment<wmma::accumulator, 16, 16, 16, float> acc[4][2];
    #pragma unroll
    for (int i = 0; i < 4; i++)
        #pragma unroll
        for (int j = 0; j < 2; j++)
            wmma::fill_fragment(acc[i][j], 0.f);

    const int nch = K >> 6;

    auto issue_loads = [&](int buf, int k0) {
        char* base = dsm + buf * GEMM_BUF_STRIDE;
        uint32_t as_s = (uint32_t)__cvta_generic_to_shared(base);
        uint32_t bs_s = as_s + 18432;
        #pragma unroll
        for (int it = 0; it < 4; it++) {
            int r = lr + it * 32;
            uint32_t doff = (uint32_t)(r * 72 + lc8 * 8) * 2;
            cp_async16(as_s + doff, A + (size_t)(bm + r) * lda + k0 + lc8 * 8);
            cp_async16(bs_s + doff, B + (size_t)(bn + r) * ldb + k0 + lc8 * 8);
        }
    };

    issue_loads(0, 0);
    cp_commit();

    for (int ch = 0; ch < nch; ch++) {
        if (ch + 1 < nch) issue_loads((ch + 1) & 1, (ch + 1) * 64);
        cp_commit();
        cp_wait1();
        __syncthreads();

        const __half (*As)[72] =
            reinterpret_cast<const __half(*)[72]>(dsm + (ch & 1) * GEMM_BUF_STRIDE);
        const __half (*Bs)[72] =
            reinterpret_cast<const __half(*)[72]>(dsm + (ch & 1) * GEMM_BUF_STRIDE + 18432);

        #pragma unroll
        for (int kk = 0; kk < 64; kk += 16) {
            wmma::fragment<wmma::matrix_a, 16, 16, 16, __half, wmma::row_major> af[4];
            wmma::fragment<wmma::matrix_b, 16, 16, 16, __half, wmma::col_major> bf[2];
            #pragma unroll
            for (int i = 0; i < 4; i++)
                wmma::load_matrix_sync(af[i], &As[warp_m * 64 + i * 16][kk], 72);
            #pragma unroll
            for (int j = 0; j < 2; j++)
                wmma::load_matrix_sync(bf[j], &Bs[warp_n * 32 + j * 16][kk], 72);
            #pragma unroll
            for (int i = 0; i < 4; i++)
                #pragma unroll
                for (int j = 0; j < 2; j++)
                    wmma::mma_sync(acc[i][j], af[i], bf[j], acc[i][j]);
        }
        __syncthreads();
    }

    // Epilogue: reuse dead smem as per-warp bounce tiles
    float* ebuf = reinterpret_cast<float*>(dsm) + wid * 256;
    const int lr2 = lane >> 1;
    const int lc2 = (lane & 1) * 8;
    #pragma unroll
    for (int i = 0; i < 4; i++)
        #pragma unroll
        for (int j = 0; j < 2; j++) {
            wmma::store_matrix_sync(ebuf, acc[i][j], 16, wmma::mem_row_major);
            __syncwarp();
            const int row = bm + warp_m * 64 + i * 16 + lr2;
            const int col = bn + warp_n * 32 + j * 16 + lc2;
            const float* src = &ebuf[lr2 * 16 + lc2];
            if (col < ncol) {
                if (OUT_HALF) {
                    __half2 hv[4];
                    #pragma unroll
                    for (int k = 0; k < 4; k++)
                        hv[k] = __floats2half2_rn(src[2 * k], src[2 * k + 1]);
                    uint4 v;
                    v.x = *(uint32_t*)&hv[0]; v.y = *(uint32_t*)&hv[1];
                    v.z = *(uint32_t*)&hv[2]; v.w = *(uint32_t*)&hv[3];
                    *(uint4*)((__half*)Cv + (size_t)row * ldc + col) = v;
                } else {
                    float4 v0 = *(const float4*)(src);
                    float4 v1 = *(const float4*)(src + 4);
                    if (bias) {
                        float4 b0 = *(const float4*)(bias + col);
                        float4 b1 = *(const float4*)(bias + col + 4);
                        v0.x += b0.x; v0.y += b0.y; v0.z += b0.z; v0.w += b0.w;
                        v1.x += b1.x; v1.y += b1.y; v1.z += b1.z; v1.w += b1.w;
                    }
                    float* cp = (float*)Cv + (size_t)row * ldc + col;
                    *(float4*)(cp)     = v0;
                    *(float4*)(cp + 4) = v1;
                }
            }
            __syncwarp();
        }
}

// ===========================================================================
// Fused conv+SiLU + x-projection GEMM.
//   A[pos][i] = silu(conv(xz[..][i]))  built on the fly (and stored to g_xch)
//   P[pos][0..39] = A[pos][:] @ xpW^T
// BM=128, N=128 (40 valid), K=256 (4 chunks of 64). grid (1, 256).
// l = (pos >> lshift) & 31; neighbor stride sL rows of xz.
// ===========================================================================
__global__ void __launch_bounds__(256)
xproj_conv_kernel(const __half* __restrict__ xz, const __half* __restrict__ Bw,
                  float* __restrict__ P, __half* __restrict__ xc,
                  const float* __restrict__ convw,  // (256,4)
                  const float* __restrict__ convb,  // (256)
                  int sL, int lshift) {
    __shared__ __half As[128][72];
    __shared__ __half Bs[128][72];
    __shared__ float ebuf[8][256];
    __shared__ float cwT[5][256];     // [cw0..cw3, cb] transposed

    const int tid = threadIdx.x;
    const int wid = tid >> 5;
    const int lane = tid & 31;
    const int warp_m = wid & 1;
    const int warp_n = wid >> 1;
    const int bm = blockIdx.y * 128;

    // Stage conv weights (transposed) + bias
    {
        float4 w = *(const float4*)(convw + tid * 4);
        cwT[0][tid] = w.x; cwT[1][tid] = w.y;
        cwT[2][tid] = w.z; cwT[3][tid] = w.w;
        cwT[4][tid] = convb[tid];
    }
    __syncthreads();

    wmma::fragment<wmma::accumulator, 16, 16, 16, float> acc[4][2];
    #pragma unroll
    for (int i = 0; i < 4; i++)
        #pragma unroll
        for (int j = 0; j < 2; j++)
            wmma::fill_fragment(acc[i][j], 0.f);

    const int c8 = tid & 7;           // constant channel group per thread

    for (int k0 = 0; k0 < 256; k0 += 64) {
        const int ich = k0 + c8 * 8;

        // B tile (xpW padded): rows 0..127, cols k0..k0+63
        #pragma unroll
        for (int it = 0; it < 4; it++) {
            int idx = tid + it * 256;
            int r = idx >> 3, cc = idx & 7;
            *(uint4*)&Bs[r][cc * 8] =
                *(const uint4*)(Bw + (size_t)r * 256 + k0 + cc * 8);
        }

        // Conv coefficients for this thread's 8 channels -> registers
        float rcw0[8], rcw1[8], rcw2[8], rcw3[8], rcb[8];
        #pragma unroll
        for (int q = 0; q < 8; q++) {
            rcw0[q] = cwT[0][ich + q]; rcw1[q] = cwT[1][ich + q];
            rcw2[q] = cwT[2][ich + q]; rcw3[q] = cwT[3][ich + q];
            rcb[q]  = cwT[4][ich + q];
        }

        // A tile: fused depthwise causal conv + SiLU
        #pragma unroll
        for (int it = 0; it < 4; it++) {
            int r = (tid >> 3) + it * 32;          // 0..127
            int pos = bm + r;
            int l = (pos >> lshift) & 31;
            const __half* bp = xz + (size_t)pos * 512 + ich;
            uint4 z4 = make_uint4(0u, 0u, 0u, 0u);
            uint4 v0 = *(const uint4*)bp;                                  // x[l]
            uint4 v1 = (l >= 1) ? *(const uint4*)(bp - (size_t)sL * 512)  : z4;  // x[l-1]
            uint4 v2 = (l >= 2) ? *(const uint4*)(bp - (size_t)sL * 1024) : z4;  // x[l-2]
            uint4 v3 = (l >= 3) ? *(const uint4*)(bp - (size_t)sL * 1536) : z4;  // x[l-3]
            const __half* h0 = (const __half*)&v0;
            const __half* h1 = (const __half*)&v1;
            const __half* h2 = (const __half*)&v2;
            const __half* h3 = (const __half*)&v3;
            union { uint4 u; __half h[8]; } res;
            #pragma unroll
            for (int q = 0; q < 8; q++) {
                float vv = rcb[q]
                    + rcw3[q] * __half2float(h0[q])
                    + rcw2[q] * __half2float(h1[q])
                    + rcw1[q] * __half2float(h2[q])
                    + rcw0[q] * __half2float(h3[q]);
                res.h[q] = __float2half(silu_f(vv));
            }
            *(uint4*)&As[r][c8 * 8] = res.u;
            *(uint4*)(xc + (size_t)pos * 256 + ich) = res.u;   // side output for scan
        }
        __syncthreads();

        #pragma unroll
        for (int kk = 0; kk < 64; kk += 16) {
            wmma::fragment<wmma::matrix_a, 16, 16, 16, __half, wmma::row_major> af[4];
            wmma::fragment<wmma::matrix_b, 16, 16, 16, __half, wmma::col_major> bf[2];
            #pragma unroll
            for (int i = 0; i < 4; i++)
                wmma::load_matrix_sync(af[i], &As[warp_m * 64 + i * 16][kk], 72);
            #pragma unroll
            for (int j = 0; j < 2; j++)
                wmma::load_matrix_sync(bf[j], &Bs[warp_n * 32 + j * 16][kk], 72);
            #pragma unroll
            for (int i = 0; i < 4; i++)
                #pragma unroll
                for (int j = 0; j < 2; j++)
                    wmma::mma_sync(acc[i][j], af[i], bf[j], acc[i][j]);
        }
        __syncthreads();
    }

    // Epilogue: fp32, ldc=40, 40 valid cols
    const int lr2 = lane >> 1;
    const int lc2 = (lane & 1) * 8;
    #pragma unroll
    for (int i = 0; i < 4; i++)
        #pragma unroll
        for (int j = 0; j < 2; j++) {
            wmma::store_matrix_sync(ebuf[wid], acc[i][j], 16, wmma::mem_row_major);
            __syncwarp();
            const int row = bm + warp_m * 64 + i * 16 + lr2;
            const int col = warp_n * 32 + j * 16 + lc2;
            const float* src = &ebuf[wid][lr2 * 16 + lc2];
            if (col < 40) {
                float* cp = P + (size_t)row * 40 + col;
                *(float4*)(cp)     = *(const float4*)(src);
                *(float4*)(cp + 4) = *(const float4*)(src + 4);
            }
            __syncwarp();
        }
}

// ---------------------------------------------------------------------------
// Merged setup kernel: cvt_x (fp32->fp16), cvt_w (inW->fp16), build_W2 (pad)
// grid = 4096 + 768 + 384 = 5248 blocks of 256.
// ---------------------------------------------------------------------------
__global__ void setup_kernel(const float* __restrict__ x,
                             const float* __restrict__ w0, const float* __restrict__ w1,
                             const float* __restrict__ w2,
                             const float* __restrict__ xp0, const float* __restrict__ xp1,
                             const float* __restrict__ xp2) {
    int blk = blockIdx.x;
    int tid = threadIdx.x;
    if (blk < 4096) {
        int idx = blk * 256 + tid;                 // float4 index, 1M total
        float4 v = ((const float4*)x)[idx];
        __half2 a = __floats2half2_rn(v.x, v.y);
        __half2 b = __floats2half2_rn(v.z, v.w);
        uint2 o;
        o.x = *(uint32_t*)&a;
        o.y = *(uint32_t*)&b;
        ((uint2*)g_xh)[idx] = o;
    } else if (blk < 4864) {
        int idx = (blk - 4096) * 256 + tid;        // 0 .. 3*65536-1
        int t = idx >> 16;
        int e = idx & 65535;
        const float* w = (t == 0) ? w0 : (t == 1) ? w1 : w2;
        g_wh[idx] = __float2half(w[e]);
    } else {
        int idx = (blk - 4864) * 256 + tid;        // 0 .. 3*32768-1
        int t = idx >> 15;
        int e = idx & 32767;
        int row = e >> 8;
        int k = e & 255;
        const float* xp = (t == 0) ? xp0 : (t == 1) ? xp1 : xp2;
        float v = (row < 40) ? xp[row * 256 + k] : 0.f;
        g_w2h[idx] = __float2half(v);
    }
}

// ---------------------------------------------------------------------------
// Fold outW_t and fcW: M[c2][t*256+j] = sum_c fcW[c2][t*128+c]*outW_t[c][j]
// grid (24,16): both operands staged in smem; pure smem FMA inner loop.
// ---------------------------------------------------------------------------
__global__ void __launch_bounds__(256)
build_M_kernel(const float* __restrict__ fcW,
               const float* __restrict__ outW_v,
               const float* __restrict__ outW_h,
               const float* __restrict__ outW_d) {
    __shared__ float oWs[128][33];
    __shared__ float frs[8][128];

    const int t  = blockIdx.x >> 3;
    const int j0 = (blockIdx.x & 7) * 32;
    const int c2base = blockIdx.y * 8;
    const int tid = threadIdx.x;

    const float* oW = (t == 0) ? outW_v : (t == 1) ? outW_h : outW_d;

    #pragma unroll
    for (int it = 0; it < 4; it++) {
        int e = tid + it * 256;
        int c = e >> 3, q = e & 7;
        float4 v = *(const float4*)(oW + c * 256 + j0 + q * 4);
        oWs[c][q * 4 + 0] = v.x; oWs[c][q * 4 + 1] = v.y;
        oWs[c][q * 4 + 2] = v.z; oWs[c][q * 4 + 3] = v.w;
    }
    {
        int r = tid >> 5, q = tid & 31;
        float4 v = *(const float4*)(fcW + (c2base + r) * 384 + t * 128 + q * 4);
        *(float4*)&frs[r][q * 4] = v;
    }
    __syncthreads();

    const int c2l = tid >> 5;
    const int jj  = tid & 31;
    float a0 = 0.f, a1 = 0.f;
    #pragma unroll 16
    for (int c = 0; c < 128; c += 2) {
        a0 += frs[c2l][c]     * oWs[c][jj];
        a1 += frs[c2l][c + 1] * oWs[c + 1][jj];
    }
    g_Mh[(c2base + c2l) * 768 + t * 256 + j0 + jj] = __float2half(a0 + a1);
}

// ---------------------------------------------------------------------------
// Lean selective scan: dt-proj (fp32) + softplus + recurrence + gating.
// grid 1024, block 256, smem ~5.1KB. P has ldc=40 (float4-staged).
// ---------------------------------------------------------------------------
__global__ void __launch_bounds__(256)
mamba_scan2_kernel(const float* __restrict__ dtW,   // (256,8)
                   const float* __restrict__ dtb,   // (256)
                   const float* __restrict__ Alog,  // (256,16)
                   const float* __restrict__ Dp,    // (256)
                   int sHi, int sLo, int sL, int branch) {
    __shared__ float dbc_s[LSEQ][40];

    const int i   = threadIdx.x;
    const int blk = blockIdx.x;
    const int base = (blk >> 5) * sHi + (blk & 31) * sLo;

    for (int idx = i; idx < LSEQ * 10; idx += 256) {
        int l = idx / 10;
        int q = idx - l * 10;
        const size_t pos = (size_t)(base + l * sL);
        *(float4*)&dbc_s[l][q * 4] = *(const float4*)(g_P + pos * 40 + q * 4);
    }
    __syncthreads();

    float Areg[NSTATE];
    #pragma unroll
    for (int n = 0; n < NSTATE; n++)
        Areg[n] = -expf(Alog[i * NSTATE + n]);

    // Structural check: A_n == (n+1)*A_0 (standard Mamba init) -> one exp/step
    bool geom = true;
    #pragma unroll
    for (int n = 0; n < NSTATE; n++)
        geom = geom && (fabsf(Areg[n] - (float)(n + 1) * Areg[0])
                        <= 1e-5f * fabsf(Areg[n]));

    float dtw[DTRANK];
    #pragma unroll
    for (int r = 0; r < DTRANK; r++) dtw[r] = dtW[i * DTRANK + r];
    const float dtbi = dtb[i];
    const float dpi  = Dp[i];

    float h[NSTATE];
    #pragma unroll
    for (int n = 0; n < NSTATE; n++) h[n] = 0.f;

    for (int l = 0; l < LSEQ; l++) {
        const size_t pos = (size_t)(base + l * sL);
        float dtv = dtbi;
        #pragma unroll
        for (int r = 0; r < DTRANK; r++) dtv += dbc_s[l][r] * dtw[r];
        dtv = (dtv > 20.f) ? dtv : __logf(1.f + __expf(dtv));

        const float u  = __half2float(g_xch[pos * 256 + i]);
        const float du = dtv * u;
        float y = 0.f;
        if (geom) {
            const float e1 = __expf(dtv * Areg[0]);
            float pw = 1.f;
            #pragma unroll
            for (int n = 0; n < NSTATE; n++) {
                pw *= e1;                                    // e1^(n+1)
                h[n] = pw * h[n] + du * dbc_s[l][DTRANK + n];
                y += h[n] * dbc_s[l][DTRANK + NSTATE + n];
            }
        } else {
            #pragma unroll
            for (int n = 0; n < NSTATE; n++) {
                float dA = __expf(dtv * Areg[n]);
                h[n] = dA * h[n] + du * dbc_s[l][DTRANK + n];
                y += h[n] * dbc_s[l][DTRANK + NSTATE + n];
            }
        }
        const float z  = __half2float(g_xzh[pos * 512 + 256 + i]);
        const float yo = (y + u * dpi) * silu_f(z);
        g_yh[pos * 768 + branch * 256 + i] = __float2half(yo);
    }
}

// ---------------------------------------------------------------------------
// Host launcher — single-stream per-branch pipeline (best known structure)
// ---------------------------------------------------------------------------
extern "C" void kernel_launch(void* const* d_in, const int* in_sizes, int n_in,
                              void* d_out, int out_size) {
    (void)in_sizes; (void)n_in; (void)out_size;

    const float* x   = (const float*)d_in[0];
    const float* prm[3][9];
    for (int t = 0; t < 3; t++)
        for (int k = 0; k < 9; k++)
            prm[t][k] = (const float*)d_in[1 + t * 9 + k];
    const float* fcW = (const float*)d_in[28];
    const float* fcb = (const float*)d_in[29];
    float* out = (float*)d_out;

    __half *xh, *wh, *xzh, *xch, *w2h, *yh, *Mh;
    float *P;
    cudaGetSymbolAddress((void**)&xh,  g_xh);
    cudaGetSymbolAddress((void**)&wh,  g_wh);
    cudaGetSymbolAddress((void**)&xzh, g_xzh);
    cudaGetSymbolAddress((void**)&xch, g_xch);
    cudaGetSymbolAddress((void**)&P,   g_P);
    cudaGetSymbolAddress((void**)&w2h, g_w2h);
    cudaGetSymbolAddress((void**)&yh,  g_yh);
    cudaGetSymbolAddress((void**)&Mh,  g_Mh);

    // One-time: raise dynamic smem limit for the double-buffered GEMM
    static bool attr_done = false;
    if (!attr_done) {
        cudaFuncSetAttribute(hgemm_db<true>,
                             cudaFuncAttributeMaxDynamicSharedMemorySize, GEMM_SMEM_TOTAL);
        cudaFuncSetAttribute(hgemm_db<false>,
                             cudaFuncAttributeMaxDynamicSharedMemorySize, GEMM_SMEM_TOTAL);
        attr_done = true;
    }

    // Merged prologue + weight folds
    setup_kernel<<<5248, 256>>>(x, prm[0][0], prm[1][0], prm[2][0],
                                prm[0][3], prm[1][3], prm[2][3]);
    build_M_kernel<<<dim3(24, 16), 256>>>(fcW, prm[0][8], prm[1][8], prm[2][8]);

    // Per-branch sequence strides:  pos = (blk>>5)*sHi + (blk&31)*sLo + l*sL
    // l = (pos >> lshift) & 31 for the fused conv inside x-proj.
    const int sHi[3]    = {  32, 1024, 1024};
    const int sLo[3]    = {   1,    1,   32};
    const int sL [3]    = {1024,   32,    1};
    const int lshift[3] = {  10,    5,    0};

    dim3 g1(512 / 128, NPOS / 128);   // in-proj: N=512
    dim3 gp(1, NPOS / 128);           // fused conv + x-proj
    for (int t = 0; t < 3; t++) {
        // xz = x @ inW_t^T  (fp16 out, double-buffered)
        hgemm_db<true><<<g1, 256, GEMM_SMEM_TOTAL>>>(xh, 128, wh + t * 512 * 128, 128,
                                                     xzh, 512, 128, nullptr, 512);
        // xc = silu(conv(xi)) fused into  dbc = xc @ xpW^T  (also writes xc)
        xproj_conv_kernel<<<gp, 256>>>(xzh, w2h + t * 128 * 256, P, xch,
                                       prm[t][1], prm[t][2], sL[t], lshift[t]);
        // recurrence
        mamba_scan2_kernel<<<1024, 256>>>(prm[t][4], prm[t][5], prm[t][6], prm[t][7],
                                          sHi[t], sLo[t], sL[t], t);
    }

    // out = yh(32768,768) @ M(128,768)^T + fcb  (fp32 out, bias fused, double-buffered)
    dim3 g2(1, NPOS / 128);
    hgemm_db<false><<<g2, 256, GEMM_SMEM_TOTAL>>>(yh, 768, Mh, 768, out, 128, 768, fcb, 128);
}